// round 11
// baseline (speedup 1.0000x reference)
#include <cuda_runtime.h>

#define HWSZ (512*512)
#define HR   42            // halo rows
#define HC   37            // halo cols per parity (74 total)
#define NSITE (HR * HC)    // 1554 sites per parity
typedef unsigned long long u64;

__device__ __forceinline__ float ex2f(float x) {
    float r; asm("ex2.approx.f32 %0, %1;" : "=f"(r) : "f"(x)); return r;
}
__device__ __forceinline__ float rcpf(float x) {
    float r; asm("rcp.approx.f32 %0, %1;" : "=f"(r) : "f"(x)); return r;
}
__device__ __forceinline__ u64 pk(float a, float b) {
    u64 r; asm("mov.b64 %0, {%1,%2};" : "=l"(r) : "f"(a), "f"(b)); return r;
}
__device__ __forceinline__ u64 mul2(u64 a, u64 b) {
    u64 r; asm("mul.rn.f32x2 %0, %1, %2;" : "=l"(r) : "l"(a), "l"(b)); return r;
}
__device__ __forceinline__ u64 fma2(u64 a, u64 b, u64 c) {
    u64 r; asm("fma.rn.f32x2 %0, %1, %2, %3;" : "=l"(r) : "l"(a), "l"(b), "l"(c)); return r;
}
__device__ __forceinline__ u64 add2(u64 a, u64 b) {
    u64 r; asm("add.rn.f32x2 %0, %1, %2;" : "=l"(r) : "l"(a), "l"(b)); return r;
}

// Tile 64 wide x 32 tall. Block (32,4)=128 thr. Each thread: 2 adjacent output
// columns (x0+2tx, x0+2tx+1) x 8 rows = 16 px.
// Shared: parity-split halo (even/odd site columns in separate dense arrays)
//   A* = (c0,c1,c2,1.0) f32 -> ulonglong2 pairs (c0,c1),(c2,1) free
//   B* = (u,u4,u9,u16) f32  -> P pairs via pk; u25 = mul2(P3,P4)
__global__ __launch_bounds__(128, 2) void GaussPSF_kernel(
    const float* __restrict__ img,
    const float* __restrict__ psf,
    float* __restrict__ out)
{
    extern __shared__ char shraw[];
    float4* Ae = reinterpret_cast<float4*>(shraw);
    float4* Ao = Ae + (NSITE + 1);
    float4* Be = Ao + (NSITE + 1);
    float4* Bo = Be + (NSITE + 1);

    const int tx = threadIdx.x;           // 0..31
    const int ty = threadIdx.y;           // 0..3
    const int tid = ty * 32 + tx;
    const int x0 = blockIdx.x * 64;
    const int y0 = blockIdx.y * 32;
    const int b  = blockIdx.z;

    const float* imb = img + (size_t)b * 3 * HWSZ;
    const float* psb = psf + (size_t)b * HWSZ;

    // ---- stage halo: one iteration handles the even+odd pixel pair ----
    for (int i = tid; i < NSITE; i += 128) {
        int sy = i / HC;
        int sx = i - sy * HC;
        int gy = y0 - 5 + sy;
        #pragma unroll
        for (int par = 0; par < 2; ++par) {
            int gx = x0 - 5 + 2 * sx + par;
            float4 ra, rb;
            if ((unsigned)gy < 512u && (unsigned)gx < 512u) {
                int p = gy * 512 + gx;
                ra.x = imb[p];
                ra.y = imb[HWSZ + p];
                ra.z = imb[2 * HWSZ + p];
                ra.w = 1.0f;
                float w = psb[p];
                float t  = fmaf(w + w, w, 1e-5f);
                float u  = ex2f(-1.4426950408889634f * rcpf(t));
                float u2 = u * u;
                float u4 = u2 * u2;
                float u8 = u4 * u4;
                rb.x = u;
                rb.y = u4;
                rb.z = u8 * u;       // u^9
                rb.w = u8 * u8;      // u^16
            } else {
                ra.x = 0.f; ra.y = 0.f; ra.z = 0.f; ra.w = 0.f;
                rb.x = 0.f; rb.y = 0.f; rb.z = 0.f; rb.w = 0.f;
            }
            if (par == 0) { Ae[i] = ra; Be[i] = rb; }
            else          { Ao[i] = ra; Bo[i] = rb; }
        }
    }
    __syncthreads();

    const ulonglong2* Ae64 = reinterpret_cast<const ulonglong2*>(Ae);
    const ulonglong2* Ao64 = reinterpret_cast<const ulonglong2*>(Ao);

    // Accumulators: L = col x0+2tx, R = col x0+2tx+1; 8 rows each
    u64 aL01[8], aL2w[8], aR01[8], aR2w[8];
    #pragma unroll
    for (int o = 0; o < 8; ++o) {
        aL01[o] = 0ull; aL2w[o] = 0ull; aR01[o] = 0ull; aR2w[o] = 0ull;
    }

    const int rowbase = ty * 8;

    #pragma unroll
    for (int s = 0; s < 18; ++s) {
        const int eb = (rowbase + s) * HC + tx;

        #pragma unroll
        for (int m = 0; m < 6; ++m) {
            // ===== EVEN site: halo col 2tx+2m; dxL=2m-5 (odd), dxR=2m-6 =====
            {
                ulonglong2 av = Ae64[eb + m];
                float4     bv = Be[eb + m];
                u64 P[6];
                P[1] = pk(bv.x, bv.x);
                P[2] = pk(bv.y, bv.y);
                P[3] = pk(bv.z, bv.z);
                P[4] = pk(bv.w, bv.w);
                P[5] = mul2(P[3], P[4]);

                const int aLd = (m < 3) ? (5 - 2 * m) : (2 * m - 5);  // 5,3,1,1,3,5
                const int aRd = (m < 3) ? (6 - 2 * m) : (2 * m - 6);  // 6,4,2,0,2,4
                const bool hasR = (m > 0);                             // |dxR|<=5

                u64 cL01 = mul2(av.x, P[aLd]);
                u64 cL2w = mul2(av.y, P[aLd]);
                u64 cR01 = 0, cR2w = 0;
                if (hasR) {
                    if (aRd == 0) { cR01 = av.x; cR2w = av.y; }
                    else { cR01 = mul2(av.x, P[aRd]); cR2w = mul2(av.y, P[aRd]); }
                }

                #pragma unroll
                for (int o = 0; o < 8; ++o) {
                    const int dy  = s - 5 - o;
                    const int dya = (dy < 0) ? -dy : dy;
                    if (dya <= 5) {
                        if (dya == 0) {
                            aL01[o] = add2(aL01[o], cL01);
                            aL2w[o] = add2(aL2w[o], cL2w);
                            if (hasR) { aR01[o] = add2(aR01[o], cR01);
                                        aR2w[o] = add2(aR2w[o], cR2w); }
                        } else {
                            aL01[o] = fma2(cL01, P[dya], aL01[o]);
                            aL2w[o] = fma2(cL2w, P[dya], aL2w[o]);
                            if (hasR) { aR01[o] = fma2(cR01, P[dya], aR01[o]);
                                        aR2w[o] = fma2(cR2w, P[dya], aR2w[o]); }
                        }
                    }
                }
            }
            // ===== ODD site: halo col 2tx+2m+1; dxL=2m-4, dxR=2m-5 (odd) =====
            {
                ulonglong2 av = Ao64[eb + m];
                float4     bv = Bo[eb + m];
                u64 P[6];
                P[1] = pk(bv.x, bv.x);
                P[2] = pk(bv.y, bv.y);
                P[3] = pk(bv.z, bv.z);
                P[4] = pk(bv.w, bv.w);
                P[5] = mul2(P[3], P[4]);

                const int aLd = (m < 2) ? (4 - 2 * m) : (2 * m - 4);  // 4,2,0,2,4,6
                const int aRd = (m < 3) ? (5 - 2 * m) : (2 * m - 5);  // 5,3,1,1,3,5
                const bool hasL = (m < 5);                             // |dxL|<=5

                u64 cR01 = mul2(av.x, P[aRd]);
                u64 cR2w = mul2(av.y, P[aRd]);
                u64 cL01 = 0, cL2w = 0;
                if (hasL) {
                    if (aLd == 0) { cL01 = av.x; cL2w = av.y; }
                    else { cL01 = mul2(av.x, P[aLd]); cL2w = mul2(av.y, P[aLd]); }
                }

                #pragma unroll
                for (int o = 0; o < 8; ++o) {
                    const int dy  = s - 5 - o;
                    const int dya = (dy < 0) ? -dy : dy;
                    if (dya <= 5) {
                        if (dya == 0) {
                            aR01[o] = add2(aR01[o], cR01);
                            aR2w[o] = add2(aR2w[o], cR2w);
                            if (hasL) { aL01[o] = add2(aL01[o], cL01);
                                        aL2w[o] = add2(aL2w[o], cL2w); }
                        } else {
                            aR01[o] = fma2(cR01, P[dya], aR01[o]);
                            aR2w[o] = fma2(cR2w, P[dya], aR2w[o]);
                            if (hasL) { aL01[o] = fma2(cL01, P[dya], aL01[o]);
                                        aL2w[o] = fma2(cL2w, P[dya], aL2w[o]); }
                        }
                    }
                }
            }
        }
    }

    // ---- normalize & write (float2 stores: columns X, X+1) ----
    float* ob = out + (size_t)b * 3 * HWSZ;
    const int X = x0 + 2 * tx;
    #pragma unroll
    for (int o = 0; o < 8; ++o) {
        float l0, l1, l2, lw, r0, r1, r2, rw;
        asm("mov.b64 {%0,%1}, %2;" : "=f"(l0), "=f"(l1) : "l"(aL01[o]));
        asm("mov.b64 {%0,%1}, %2;" : "=f"(l2), "=f"(lw) : "l"(aL2w[o]));
        asm("mov.b64 {%0,%1}, %2;" : "=f"(r0), "=f"(r1) : "l"(aR01[o]));
        asm("mov.b64 {%0,%1}, %2;" : "=f"(r2), "=f"(rw) : "l"(aR2w[o]));
        float il = rcpf(lw);
        float ir = rcpf(rw);
        int y = y0 + rowbase + o;
        int p = y * 512 + X;
        *reinterpret_cast<float2*>(ob + p)            = make_float2(l0 * il, r0 * ir);
        *reinterpret_cast<float2*>(ob + HWSZ + p)     = make_float2(l1 * il, r1 * ir);
        *reinterpret_cast<float2*>(ob + 2 * HWSZ + p) = make_float2(l2 * il, r2 * ir);
    }
}

extern "C" void kernel_launch(void* const* d_in, const int* in_sizes, int n_in,
                              void* d_out, int out_size)
{
    const float* img = (const float*)d_in[0];   // (4,3,512,512) f32
    const float* psf = (const float*)d_in[1];   // (4,512,512)   f32
    float* out = (float*)d_out;                 // (4,3,512,512) f32

    const int smem = 4 * (NSITE + 1) * (int)sizeof(float4);   // 99520 B
    cudaFuncSetAttribute(GaussPSF_kernel,
                         cudaFuncAttributeMaxDynamicSharedMemorySize, smem);

    dim3 block(32, 4, 1);
    dim3 grid(512 / 64, 512 / 32, 4);
    GaussPSF_kernel<<<grid, block, smem>>>(img, psf, out);
}